// round 10
// baseline (speedup 1.0000x reference)
#include <cuda_runtime.h>
#include <cuda_bf16.h>
#include <cstdint>
#include <math_constants.h>

#define NTOK 4096
#define DIN  1024
#define DH   512
#define PV_SPLITS 4

// ---------------------------------------------------------------------------
// Scratch (__device__ globals; no allocation allowed)
// ---------------------------------------------------------------------------
__device__ __nv_bfloat16 g_Eh[(size_t)NTOK * DIN];
__device__ __nv_bfloat16 g_El[(size_t)NTOK * DIN];
__device__ __nv_bfloat16 g_Wqh[(size_t)DH * DIN];
__device__ __nv_bfloat16 g_Wql[(size_t)DH * DIN];
__device__ __nv_bfloat16 g_Wkh[(size_t)DH * DIN];
__device__ __nv_bfloat16 g_Wkl[(size_t)DH * DIN];
__device__ __nv_bfloat16 g_Wvh[(size_t)DH * DIN];
__device__ __nv_bfloat16 g_Wvl[(size_t)DH * DIN];
__device__ __nv_bfloat16 g_Qh[(size_t)NTOK * DH];
__device__ __nv_bfloat16 g_Ql[(size_t)NTOK * DH];
__device__ __nv_bfloat16 g_Kh[(size_t)NTOK * DH];
__device__ __nv_bfloat16 g_Kl[(size_t)NTOK * DH];
__device__ __nv_bfloat16 g_VtH[(size_t)DH * NTOK];
__device__ __nv_bfloat16 g_VtL[(size_t)DH * NTOK];
__device__ float         g_S[(size_t)NTOK * NTOK];
__device__ __nv_bfloat16 g_Ph[(size_t)NTOK * NTOK];
__device__ __nv_bfloat16 g_Pl[(size_t)NTOK * NTOK];
__device__ float         g_PV[(size_t)PV_SPLITS * NTOK * DH];

// ---------------------------------------------------------------------------
// PTX helpers (sm_80-level: valid under compute_103 virtual arch)
// ---------------------------------------------------------------------------
__device__ __forceinline__ uint32_t smem_u32(const void* p) {
    uint32_t a;
    asm("{ .reg .u64 t; cvta.to.shared.u64 t, %1; cvt.u32.u64 %0, t; }"
        : "=r"(a) : "l"(p));
    return a;
}

__device__ __forceinline__ void cp16(uint32_t dst, const void* src) {
    asm volatile("cp.async.cg.shared.global [%0], [%1], 16;"
                 :: "r"(dst), "l"(src) : "memory");
}
#define CP_COMMIT() asm volatile("cp.async.commit_group;" ::: "memory")
#define CP_WAIT(n)  asm volatile("cp.async.wait_group %0;" :: "n"(n) : "memory")

#define LDSM4(r0, r1, r2, r3, addr)                                            \
    asm volatile("ldmatrix.sync.aligned.m8n8.x4.shared.b16 {%0,%1,%2,%3}, [%4];" \
                 : "=r"(r0), "=r"(r1), "=r"(r2), "=r"(r3) : "r"(addr))

#define MMA_BF16(c, a, b0, b1)                                                 \
    asm volatile("mma.sync.aligned.m16n8k16.row.col.f32.bf16.bf16.f32 "        \
                 "{%0,%1,%2,%3}, {%4,%5,%6,%7}, {%8,%9}, {%0,%1,%2,%3};"       \
                 : "+f"((c)[0]), "+f"((c)[1]), "+f"((c)[2]), "+f"((c)[3])      \
                 : "r"((a)[0]), "r"((a)[1]), "r"((a)[2]), "r"((a)[3]),         \
                   "r"(b0), "r"(b1))

__device__ __forceinline__ uint32_t sw(uint32_t off) {
    return off ^ ((off >> 3) & 0x70);
}

// ---------------------------------------------------------------------------
// hi/lo split conversion (fp32 -> bf16 hi + bf16 lo)
// ---------------------------------------------------------------------------
__device__ __forceinline__ void split4(float4 v, __nv_bfloat162* h, __nv_bfloat162* l,
                                       int i)
{
    __nv_bfloat16 hx = __float2bfloat16(v.x);
    __nv_bfloat16 hy = __float2bfloat16(v.y);
    __nv_bfloat16 hz = __float2bfloat16(v.z);
    __nv_bfloat16 hw = __float2bfloat16(v.w);
    h[2 * i + 0] = __nv_bfloat162(hx, hy);
    h[2 * i + 1] = __nv_bfloat162(hz, hw);
    l[2 * i + 0] = __nv_bfloat162(__float2bfloat16(v.x - __bfloat162float(hx)),
                                  __float2bfloat16(v.y - __bfloat162float(hy)));
    l[2 * i + 1] = __nv_bfloat162(__float2bfloat16(v.z - __bfloat162float(hz)),
                                  __float2bfloat16(v.w - __bfloat162float(hw)));
}

__global__ void split_f32(const float4* __restrict__ x,
                          __nv_bfloat162* __restrict__ h,
                          __nv_bfloat162* __restrict__ l, int n4)
{
    for (int i = blockIdx.x * blockDim.x + threadIdx.x; i < n4;
         i += gridDim.x * blockDim.x)
        split4(x[i], h, l, i);
}

__global__ void split_w3(const float4* __restrict__ Wq, const float4* __restrict__ Wk,
                         const float4* __restrict__ Wv,
                         __nv_bfloat162* __restrict__ qh, __nv_bfloat162* __restrict__ ql,
                         __nv_bfloat162* __restrict__ kh, __nv_bfloat162* __restrict__ kl,
                         __nv_bfloat162* __restrict__ vh, __nv_bfloat162* __restrict__ vl,
                         int n4)
{
    const int z = blockIdx.z;
    const float4* x = (z == 0) ? Wq : (z == 1) ? Wk : Wv;
    __nv_bfloat162* h = (z == 0) ? qh : (z == 1) ? kh : vh;
    __nv_bfloat162* l = (z == 0) ? ql : (z == 1) ? kl : vl;
    for (int i = blockIdx.x * blockDim.x + threadIdx.x; i < n4;
         i += gridDim.x * blockDim.x)
        split4(x[i], h, l, i);
}

// ---------------------------------------------------------------------------
// GEMM body: C = Ah·Bh^T + Ah·Bl^T + Al·Bh^T over K from kbase.
// 3-stage cp.async pipeline, ONE __syncthreads per chunk.
// 512 threads, 16 warps (8 M-groups x 2 N-halves), warp tile 16x64,
// CTA tile 128x128, K-chunk 64. Occupancy-driven latency hiding (4 warps/SMSP).
// epi: 0 = fp32 C, 1 = split (Ch,Cl) [M,N], 2 = split transposed [N,M]
// ---------------------------------------------------------------------------
#define KCH 64
#define TILE_BYTES  16384          // 128 rows x 128B
#define STAGE_BYTES 65536          // Ah | Al | Bh | Bl
#define NSTAGE 3
#define SMEM_BYTES  (NSTAGE * STAGE_BYTES)   // 192 KB
#define NTHREADS 512

__device__ __forceinline__ void load_tile(uint32_t sbase, const __nv_bfloat16* g,
                                          int ld, int row0, int k0, int tid)
{
    const char* gp = (const char*)(g + (size_t)row0 * ld + k0);
    size_t ldb = (size_t)ld * 2;
    #pragma unroll
    for (int i = 0; i < 2; i++) {
        int idx = tid + i * NTHREADS;       // 0..1023
        int r = idx >> 3, j = idx & 7;
        uint32_t off = (uint32_t)(r * 128 + j * 16);
        cp16(sbase + sw(off), gp + (size_t)r * ldb + j * 16);
    }
}

__device__ __forceinline__ void gemm3x_body(
    const __nv_bfloat16* __restrict__ Ah, const __nv_bfloat16* __restrict__ Al,
    const __nv_bfloat16* __restrict__ Bh, const __nv_bfloat16* __restrict__ Bl,
    const float* __restrict__ bias,
    float* __restrict__ Cf,
    __nv_bfloat16* __restrict__ Ch, __nv_bfloat16* __restrict__ Cl,
    int M, int N, int K, int ldA, int ldB, int kbase, int epi, char* smem)
{
    const uint32_t sb = smem_u32(smem);

    const int tid  = threadIdx.x;
    const int wid  = tid >> 5;
    const int lane = tid & 31;
    const int wm   = wid >> 1;          // 0..7 -> 16-row group
    const int wn   = wid & 1;           // 0..1 -> 64-col half
    const int bm   = blockIdx.y * 128;
    const int bn   = blockIdx.x * 128;

    float acc[8][4];
    #pragma unroll
    for (int j = 0; j < 8; j++)
        #pragma unroll
        for (int t = 0; t < 4; t++) acc[j][t] = 0.0f;

    const int KC = K / KCH;

    const int a_row = wm * 16 + (lane & 15);
    const int a_seg = (lane >> 4);
    const int b_row = wn * 64 + (lane & 7) + ((lane >> 4) << 3);
    const int b_seg = ((lane >> 3) & 1);

    auto load_chunk = [&](uint32_t stg, int c) {
        const int k0 = kbase + c * KCH;
        load_tile(stg,                  Ah, ldA, bm, k0, tid);
        load_tile(stg + TILE_BYTES,     Al, ldA, bm, k0, tid);
        load_tile(stg + 2 * TILE_BYTES, Bh, ldB, bn, k0, tid);
        load_tile(stg + 3 * TILE_BYTES, Bl, ldB, bn, k0, tid);
    };

    // prologue: 2 chunks in flight
    load_chunk(sb, 0);
    CP_COMMIT();
    if (KC > 1) load_chunk(sb + STAGE_BYTES, 1);
    CP_COMMIT();

    for (int c = 0; c < KC; c++) {
        if (c + 1 < KC) { CP_WAIT(1); } else { CP_WAIT(0); }
        __syncthreads();    // stage c%3 ready; everyone done reading stage (c+2)%3

        // loads for chunk c+2 overlap the MMAs below
        if (c + 2 < KC)
            load_chunk(sb + (uint32_t)((c + 2) % NSTAGE) * STAGE_BYTES, c + 2);
        CP_COMMIT();

        const uint32_t stg = sb + (uint32_t)(c % NSTAGE) * STAGE_BYTES;
        const uint32_t saH = stg;
        const uint32_t saL = stg + TILE_BYTES;
        const uint32_t sbH = stg + 2 * TILE_BYTES;
        const uint32_t sbL = stg + 3 * TILE_BYTES;

        #pragma unroll
        for (int ks = 0; ks < 4; ks++) {
            uint32_t aH[4], aL[4];
            {
                uint32_t so = sw((uint32_t)(a_row * 128 + (ks * 2 + a_seg) * 16));
                LDSM4(aH[0], aH[1], aH[2], aH[3], saH + so);
                LDSM4(aL[0], aL[1], aL[2], aL[3], saL + so);
            }
            uint32_t bH[4][4], bL[4][4];
            #pragma unroll
            for (int ng = 0; ng < 4; ng++) {
                uint32_t so = sw((uint32_t)((b_row + ng * 16) * 128 +
                                            (ks * 2 + b_seg) * 16));
                LDSM4(bH[ng][0], bH[ng][1], bH[ng][2], bH[ng][3], sbH + so);
                LDSM4(bL[ng][0], bL[ng][1], bL[ng][2], bL[ng][3], sbL + so);
            }
            #pragma unroll
            for (int nj = 0; nj < 8; nj++) {
                const int ng = nj >> 1, hp = (nj & 1) << 1;
                MMA_BF16(acc[nj], aH, bH[ng][hp], bH[ng][hp + 1]);
            }
            #pragma unroll
            for (int nj = 0; nj < 8; nj++) {
                const int ng = nj >> 1, hp = (nj & 1) << 1;
                MMA_BF16(acc[nj], aL, bH[ng][hp], bH[ng][hp + 1]);
            }
            #pragma unroll
            for (int nj = 0; nj < 8; nj++) {
                const int ng = nj >> 1, hp = (nj & 1) << 1;
                MMA_BF16(acc[nj], aH, bL[ng][hp], bL[ng][hp + 1]);
            }
        }
        // no trailing sync: next iteration's top sync protects stage reuse
    }

    // ---------------- epilogue ----------------
    const int r0  = (lane >> 2);
    const int cth = 2 * (lane & 3);
    #pragma unroll
    for (int nj = 0; nj < 8; nj++) {
        const int col = bn + wn * 64 + nj * 8 + cth;
        float v0 = acc[nj][0], v1 = acc[nj][1];
        float v2 = acc[nj][2], v3 = acc[nj][3];
        if (bias) {
            float b0 = bias[col], b1 = bias[col + 1];
            v0 += b0; v1 += b1; v2 += b0; v3 += b1;
        }
        const int rowA = bm + wm * 16 + r0;
        const int rowB = rowA + 8;
        if (epi == 0) {
            *(float2*)&Cf[(size_t)rowA * N + col] = make_float2(v0, v1);
            *(float2*)&Cf[(size_t)rowB * N + col] = make_float2(v2, v3);
        } else {
            __nv_bfloat16 h0 = __float2bfloat16(v0);
            __nv_bfloat16 h1 = __float2bfloat16(v1);
            __nv_bfloat16 h2 = __float2bfloat16(v2);
            __nv_bfloat16 h3 = __float2bfloat16(v3);
            __nv_bfloat16 l0 = __float2bfloat16(v0 - __bfloat162float(h0));
            __nv_bfloat16 l1 = __float2bfloat16(v1 - __bfloat162float(h1));
            __nv_bfloat16 l2 = __float2bfloat16(v2 - __bfloat162float(h2));
            __nv_bfloat16 l3 = __float2bfloat16(v3 - __bfloat162float(h3));
            if (epi == 1) {
                *(__nv_bfloat162*)&Ch[(size_t)rowA * N + col] = __nv_bfloat162(h0, h1);
                *(__nv_bfloat162*)&Ch[(size_t)rowB * N + col] = __nv_bfloat162(h2, h3);
                *(__nv_bfloat162*)&Cl[(size_t)rowA * N + col] = __nv_bfloat162(l0, l1);
                *(__nv_bfloat162*)&Cl[(size_t)rowB * N + col] = __nv_bfloat162(l2, l3);
            } else {
                Ch[(size_t)col * M + rowA]       = h0;
                Ch[(size_t)(col + 1) * M + rowA] = h1;
                Ch[(size_t)col * M + rowB]       = h2;
                Ch[(size_t)(col + 1) * M + rowB] = h3;
                Cl[(size_t)col * M + rowA]       = l0;
                Cl[(size_t)(col + 1) * M + rowA] = l1;
                Cl[(size_t)col * M + rowB]       = l2;
                Cl[(size_t)(col + 1) * M + rowB] = l3;
            }
        }
    }
}

// ---------------------------------------------------------------------------
// Kernel wrappers
// ---------------------------------------------------------------------------
__global__ __launch_bounds__(NTHREADS, 1)
void proj_qkv(const __nv_bfloat16* __restrict__ Eh, const __nv_bfloat16* __restrict__ El,
              const __nv_bfloat16* __restrict__ Wqh, const __nv_bfloat16* __restrict__ Wql,
              const __nv_bfloat16* __restrict__ Wkh, const __nv_bfloat16* __restrict__ Wkl,
              const __nv_bfloat16* __restrict__ Wvh, const __nv_bfloat16* __restrict__ Wvl,
              const float* __restrict__ bq, const float* __restrict__ bk,
              const float* __restrict__ bv,
              __nv_bfloat16* __restrict__ Qh, __nv_bfloat16* __restrict__ Ql,
              __nv_bfloat16* __restrict__ Kh, __nv_bfloat16* __restrict__ Kl,
              __nv_bfloat16* __restrict__ VtH, __nv_bfloat16* __restrict__ VtL)
{
    extern __shared__ char smem[];
    const int z = blockIdx.z;
    const __nv_bfloat16* Bh = (z == 0) ? Wqh : (z == 1) ? Wkh : Wvh;
    const __nv_bfloat16* Bl = (z == 0) ? Wql : (z == 1) ? Wkl : Wvl;
    const float* bias       = (z == 0) ? bq  : (z == 1) ? bk  : bv;
    __nv_bfloat16* Ch       = (z == 0) ? Qh  : (z == 1) ? Kh  : VtH;
    __nv_bfloat16* Cl       = (z == 0) ? Ql  : (z == 1) ? Kl  : VtL;
    const int epi = (z == 2) ? 2 : 1;
    gemm3x_body(Eh, El, Bh, Bl, bias, nullptr, Ch, Cl,
                NTOK, DH, DIN, DIN, DIN, 0, epi, smem);
}

__global__ __launch_bounds__(NTHREADS, 1)
void score_gemm(const __nv_bfloat16* __restrict__ Qh, const __nv_bfloat16* __restrict__ Ql,
                const __nv_bfloat16* __restrict__ Kh, const __nv_bfloat16* __restrict__ Kl,
                float* __restrict__ S)
{
    extern __shared__ char smem[];
    gemm3x_body(Qh, Ql, Kh, Kl, nullptr, S, nullptr, nullptr,
                NTOK, NTOK, DH, DH, DH, 0, 0, smem);
}

__global__ __launch_bounds__(NTHREADS, 1)
void pv_gemm(const __nv_bfloat16* __restrict__ Ph, const __nv_bfloat16* __restrict__ Pl,
             const __nv_bfloat16* __restrict__ VtH, const __nv_bfloat16* __restrict__ VtL,
             float* __restrict__ partials)
{
    extern __shared__ char smem[];
    const int z = blockIdx.z;
    const int ksplit = NTOK / PV_SPLITS;     // 1024
    float* Cf = partials + (size_t)z * NTOK * DH;
    gemm3x_body(Ph, Pl, VtH, VtL, nullptr, Cf, nullptr, nullptr,
                NTOK, DH, ksplit, NTOK, NTOK, z * ksplit, 0, smem);
}

__global__ __launch_bounds__(256)
void reduce_pv(const float4* __restrict__ p, float4* __restrict__ out, int n4)
{
    int i = blockIdx.x * blockDim.x + threadIdx.x;
    if (i < n4) {
        float4 a = p[i];
        float4 b = p[i + n4];
        float4 c = p[i + 2 * n4];
        float4 d = p[i + 3 * n4];
        out[i] = make_float4(a.x + b.x + c.x + d.x, a.y + b.y + c.y + d.y,
                             a.z + b.z + c.z + d.z, a.w + b.w + c.w + d.w);
    }
}

// ---------------------------------------------------------------------------
// Row softmax over S[NTOK, NTOK], writes split bf16 P. 1 CTA/row.
// ---------------------------------------------------------------------------
__global__ __launch_bounds__(256)
void softmax_split(const float* __restrict__ S,
                   __nv_bfloat16* __restrict__ Ph, __nv_bfloat16* __restrict__ Pl)
{
    const int row = blockIdx.x;
    const float* p = S + (size_t)row * NTOK;
    const int tid = threadIdx.x;

    float vals[16];
    float m = -CUDART_INF_F;
    #pragma unroll
    for (int i = 0; i < 16; i++) {
        vals[i] = p[tid + i * 256];
        m = fmaxf(m, vals[i]);
    }

    __shared__ float red[8];
    #pragma unroll
    for (int o = 16; o > 0; o >>= 1)
        m = fmaxf(m, __shfl_xor_sync(0xffffffffu, m, o));
    if ((tid & 31) == 0) red[tid >> 5] = m;
    __syncthreads();
    if (tid < 32) {
        float x = (tid < 8) ? red[tid] : -CUDART_INF_F;
        #pragma unroll
        for (int o = 4; o > 0; o >>= 1)
            x = fmaxf(x, __shfl_xor_sync(0xffffffffu, x, o));
        if (tid == 0) red[0] = x;
    }
    __syncthreads();
    m = red[0];
    __syncthreads();

    float s = 0.0f;
    #pragma unroll
    for (int i = 0; i < 16; i++) {
        vals[i] = __expf(vals[i] - m);
        s += vals[i];
    }
    #pragma unroll
    for (int o = 16; o > 0; o >>= 1)
        s += __shfl_xor_sync(0xffffffffu, s, o);
    if ((tid & 31) == 0) red[tid >> 5] = s;
    __syncthreads();
    if (tid < 32) {
        float x = (tid < 8) ? red[tid] : 0.0f;
        #pragma unroll
        for (int o = 4; o > 0; o >>= 1)
            x += __shfl_xor_sync(0xffffffffu, x, o);
        if (tid == 0) red[0] = x;
    }
    __syncthreads();
    const float inv = 1.0f / red[0];

    __nv_bfloat16* ph = Ph + (size_t)row * NTOK;
    __nv_bfloat16* pl = Pl + (size_t)row * NTOK;
    #pragma unroll
    for (int i = 0; i < 16; i++) {
        float pv = vals[i] * inv;
        __nv_bfloat16 h = __float2bfloat16(pv);
        ph[tid + i * 256] = h;
        pl[tid + i * 256] = __float2bfloat16(pv - __bfloat162float(h));
    }
}

// ---------------------------------------------------------------------------
// Host launch
// ---------------------------------------------------------------------------
extern "C" void kernel_launch(void* const* d_in, const int* in_sizes, int n_in,
                              void* d_out, int out_size)
{
    const float* embs = (const float*)d_in[0];
    const float* Wq   = (const float*)d_in[1];
    const float* bq   = (const float*)d_in[2];
    const float* Wk   = (const float*)d_in[3];
    const float* bk   = (const float*)d_in[4];
    const float* Wv   = (const float*)d_in[5];
    const float* bv   = (const float*)d_in[6];
    float* out = (float*)d_out;

    __nv_bfloat16 *Eh, *El, *Wqh, *Wql, *Wkh, *Wkl, *Wvh, *Wvl;
    __nv_bfloat16 *Qh, *Ql, *Kh, *Kl, *VtH, *VtL, *Ph, *Pl;
    float *S, *PV;
    cudaGetSymbolAddress((void**)&Eh, g_Eh);   cudaGetSymbolAddress((void**)&El, g_El);
    cudaGetSymbolAddress((void**)&Wqh, g_Wqh); cudaGetSymbolAddress((void**)&Wql, g_Wql);
    cudaGetSymbolAddress((void**)&Wkh, g_Wkh); cudaGetSymbolAddress((void**)&Wkl, g_Wkl);
    cudaGetSymbolAddress((void**)&Wvh, g_Wvh); cudaGetSymbolAddress((void**)&Wvl, g_Wvl);
    cudaGetSymbolAddress((void**)&Qh, g_Qh);   cudaGetSymbolAddress((void**)&Ql, g_Ql);
    cudaGetSymbolAddress((void**)&Kh, g_Kh);   cudaGetSymbolAddress((void**)&Kl, g_Kl);
    cudaGetSymbolAddress((void**)&VtH, g_VtH); cudaGetSymbolAddress((void**)&VtL, g_VtL);
    cudaGetSymbolAddress((void**)&S, g_S);
    cudaGetSymbolAddress((void**)&Ph, g_Ph);   cudaGetSymbolAddress((void**)&Pl, g_Pl);
    cudaGetSymbolAddress((void**)&PV, g_PV);

    cudaFuncSetAttribute(proj_qkv,   cudaFuncAttributeMaxDynamicSharedMemorySize, SMEM_BYTES);
    cudaFuncSetAttribute(score_gemm, cudaFuncAttributeMaxDynamicSharedMemorySize, SMEM_BYTES);
    cudaFuncSetAttribute(pv_gemm,    cudaFuncAttributeMaxDynamicSharedMemorySize, SMEM_BYTES);

    // 1) hi/lo splits
    split_f32<<<2048, 256>>>((const float4*)embs, (__nv_bfloat162*)Eh,
                             (__nv_bfloat162*)El, NTOK * DIN / 4);
    dim3 g_w(256, 1, 3);
    split_w3<<<g_w, 256>>>((const float4*)Wq, (const float4*)Wk, (const float4*)Wv,
                           (__nv_bfloat162*)Wqh, (__nv_bfloat162*)Wql,
                           (__nv_bfloat162*)Wkh, (__nv_bfloat162*)Wkl,
                           (__nv_bfloat162*)Wvh, (__nv_bfloat162*)Wvl,
                           DH * DIN / 4);

    // 2) Q/K/V projections in ONE launch (384 CTAs)
    dim3 g_proj(DH / 128, NTOK / 128, 3);
    proj_qkv<<<g_proj, NTHREADS, SMEM_BYTES>>>(Eh, El, Wqh, Wql, Wkh, Wkl, Wvh, Wvl,
                                               bq, bk, bv, Qh, Ql, Kh, Kl, VtH, VtL);

    // 3) scores S = Q @ K^T (1024 CTAs)
    dim3 g_s(NTOK / 128, NTOK / 128);
    score_gemm<<<g_s, NTHREADS, SMEM_BYTES>>>(Qh, Ql, Kh, Kl, S);

    // 4) softmax + P split
    softmax_split<<<NTOK, 256>>>(S, Ph, Pl);

    // 5) PV split-K (512 CTAs) + reduce
    dim3 g_pv(DH / 128, NTOK / 128, PV_SPLITS);
    pv_gemm<<<g_pv, NTHREADS, SMEM_BYTES>>>(Ph, Pl, VtH, VtL, PV);
    const int n4 = NTOK * DH / 4;
    reduce_pv<<<(n4 + 255) / 256, 256>>>((const float4*)PV, (float4*)out, n4);
}

// round 11
// speedup vs baseline: 1.0742x; 1.0742x over previous
#include <cuda_runtime.h>
#include <cuda_bf16.h>
#include <cstdint>
#include <math_constants.h>

#define NTOK 4096
#define DIN  1024
#define DH   512

// ---------------------------------------------------------------------------
// Scratch (__device__ globals; no allocation allowed)
// ---------------------------------------------------------------------------
__device__ __nv_bfloat16 g_Eh[(size_t)NTOK * DIN];
__device__ __nv_bfloat16 g_El[(size_t)NTOK * DIN];
__device__ __nv_bfloat16 g_Wqh[(size_t)DH * DIN];
__device__ __nv_bfloat16 g_Wql[(size_t)DH * DIN];
__device__ __nv_bfloat16 g_Wkh[(size_t)DH * DIN];
__device__ __nv_bfloat16 g_Wkl[(size_t)DH * DIN];
__device__ __nv_bfloat16 g_Wvh[(size_t)DH * DIN];
__device__ __nv_bfloat16 g_Wvl[(size_t)DH * DIN];
__device__ __nv_bfloat16 g_Qh[(size_t)NTOK * DH];
__device__ __nv_bfloat16 g_Ql[(size_t)NTOK * DH];
__device__ __nv_bfloat16 g_Kh[(size_t)NTOK * DH];
__device__ __nv_bfloat16 g_Kl[(size_t)NTOK * DH];
__device__ __nv_bfloat16 g_VtH[(size_t)DH * NTOK];
__device__ __nv_bfloat16 g_VtL[(size_t)DH * NTOK];
__device__ float         g_S[(size_t)NTOK * NTOK];
__device__ __nv_bfloat16 g_Ph[(size_t)NTOK * NTOK];
__device__ __nv_bfloat16 g_Pl[(size_t)NTOK * NTOK];

// ---------------------------------------------------------------------------
// PTX helpers (sm_80-level: valid under compute_103 virtual arch)
// ---------------------------------------------------------------------------
__device__ __forceinline__ uint32_t smem_u32(const void* p) {
    uint32_t a;
    asm("{ .reg .u64 t; cvta.to.shared.u64 t, %1; cvt.u32.u64 %0, t; }"
        : "=r"(a) : "l"(p));
    return a;
}

__device__ __forceinline__ void cp16(uint32_t dst, const void* src) {
    asm volatile("cp.async.cg.shared.global [%0], [%1], 16;"
                 :: "r"(dst), "l"(src) : "memory");
}
#define CP_COMMIT() asm volatile("cp.async.commit_group;" ::: "memory")
#define CP_WAIT(n)  asm volatile("cp.async.wait_group %0;" :: "n"(n) : "memory")

#define LDSM4(r0, r1, r2, r3, addr)                                            \
    asm volatile("ldmatrix.sync.aligned.m8n8.x4.shared.b16 {%0,%1,%2,%3}, [%4];" \
                 : "=r"(r0), "=r"(r1), "=r"(r2), "=r"(r3) : "r"(addr))

#define MMA_BF16(c, a, b0, b1)                                                 \
    asm volatile("mma.sync.aligned.m16n8k16.row.col.f32.bf16.bf16.f32 "        \
                 "{%0,%1,%2,%3}, {%4,%5,%6,%7}, {%8,%9}, {%0,%1,%2,%3};"       \
                 : "+f"((c)[0]), "+f"((c)[1]), "+f"((c)[2]), "+f"((c)[3])      \
                 : "r"((a)[0]), "r"((a)[1]), "r"((a)[2]), "r"((a)[3]),         \
                   "r"(b0), "r"(b1))

__device__ __forceinline__ uint32_t sw(uint32_t off) {
    return off ^ ((off >> 3) & 0x70);
}

// ---------------------------------------------------------------------------
// hi/lo split conversion (fp32 -> bf16 hi + bf16 lo)
// ---------------------------------------------------------------------------
__device__ __forceinline__ void split4(float4 v, __nv_bfloat162* h, __nv_bfloat162* l,
                                       int i)
{
    __nv_bfloat16 hx = __float2bfloat16(v.x);
    __nv_bfloat16 hy = __float2bfloat16(v.y);
    __nv_bfloat16 hz = __float2bfloat16(v.z);
    __nv_bfloat16 hw = __float2bfloat16(v.w);
    h[2 * i + 0] = __nv_bfloat162(hx, hy);
    h[2 * i + 1] = __nv_bfloat162(hz, hw);
    l[2 * i + 0] = __nv_bfloat162(__float2bfloat16(v.x - __bfloat162float(hx)),
                                  __float2bfloat16(v.y - __bfloat162float(hy)));
    l[2 * i + 1] = __nv_bfloat162(__float2bfloat16(v.z - __bfloat162float(hz)),
                                  __float2bfloat16(v.w - __bfloat162float(hw)));
}

__global__ void split_f32(const float4* __restrict__ x,
                          __nv_bfloat162* __restrict__ h,
                          __nv_bfloat162* __restrict__ l, int n4)
{
    for (int i = blockIdx.x * blockDim.x + threadIdx.x; i < n4;
         i += gridDim.x * blockDim.x)
        split4(x[i], h, l, i);
}

__global__ void split_w3(const float4* __restrict__ Wq, const float4* __restrict__ Wk,
                         const float4* __restrict__ Wv,
                         __nv_bfloat162* __restrict__ qh, __nv_bfloat162* __restrict__ ql,
                         __nv_bfloat162* __restrict__ kh, __nv_bfloat162* __restrict__ kl,
                         __nv_bfloat162* __restrict__ vh, __nv_bfloat162* __restrict__ vl,
                         int n4)
{
    const int z = blockIdx.z;
    const float4* x = (z == 0) ? Wq : (z == 1) ? Wk : Wv;
    __nv_bfloat162* h = (z == 0) ? qh : (z == 1) ? kh : vh;
    __nv_bfloat162* l = (z == 0) ? ql : (z == 1) ? kl : vl;
    for (int i = blockIdx.x * blockDim.x + threadIdx.x; i < n4;
         i += gridDim.x * blockDim.x)
        split4(x[i], h, l, i);
}

// ---------------------------------------------------------------------------
// GEMM body: C = Ah·Bh^T + Ah·Bl^T + Al·Bh^T over K from kbase.
// 3-stage cp.async pipeline, ONE __syncthreads per chunk, register
// double-buffered fragments. CTA 128x128, 8 warps (4x2), warp tile 32x64.
// epi: 0 = fp32 C, 1 = split (Ch,Cl) [M,N], 2 = split transposed [N,M]
// ---------------------------------------------------------------------------
#define KCH 64
#define TILE_BYTES  16384          // 128 rows x 128B
#define STAGE_BYTES 65536          // Ah | Al | Bh | Bl
#define NSTAGE 3
#define SMEM_BYTES  (NSTAGE * STAGE_BYTES)   // 192 KB

__device__ __forceinline__ void load_tile(uint32_t sbase, const __nv_bfloat16* g,
                                          int ld, int row0, int k0, int tid)
{
    const char* gp = (const char*)(g + (size_t)row0 * ld + k0);
    size_t ldb = (size_t)ld * 2;
    #pragma unroll
    for (int i = 0; i < 4; i++) {
        int idx = tid + i * 256;
        int r = idx >> 3, j = idx & 7;
        uint32_t off = (uint32_t)(r * 128 + j * 16);
        cp16(sbase + sw(off), gp + (size_t)r * ldb + j * 16);
    }
}

__device__ __forceinline__ void gemm3x_body(
    const __nv_bfloat16* __restrict__ Ah, const __nv_bfloat16* __restrict__ Al,
    const __nv_bfloat16* __restrict__ Bh, const __nv_bfloat16* __restrict__ Bl,
    const float* __restrict__ bias,
    float* __restrict__ Cf,
    __nv_bfloat16* __restrict__ Ch, __nv_bfloat16* __restrict__ Cl,
    int M, int N, int K, int ldA, int ldB, int kbase, int epi, char* smem)
{
    const uint32_t sb = smem_u32(smem);

    const int tid  = threadIdx.x;
    const int wid  = tid >> 5;
    const int lane = tid & 31;
    const int wm   = wid >> 1;          // 0..3
    const int wn   = wid & 1;           // 0..1
    const int bm   = blockIdx.y * 128;
    const int bn   = blockIdx.x * 128;

    float acc[2][8][4];
    #pragma unroll
    for (int i = 0; i < 2; i++)
        #pragma unroll
        for (int j = 0; j < 8; j++)
            #pragma unroll
            for (int t = 0; t < 4; t++) acc[i][j][t] = 0.0f;

    const int KC = K / KCH;

    const int a_row = wm * 32 + (lane & 15);
    const int a_seg = (lane >> 4);
    const int b_row = wn * 64 + (lane & 7) + ((lane >> 4) << 3);
    const int b_seg = ((lane >> 3) & 1);

    auto load_chunk = [&](uint32_t stg, int c) {
        const int k0 = kbase + c * KCH;
        load_tile(stg,                  Ah, ldA, bm, k0, tid);
        load_tile(stg + TILE_BYTES,     Al, ldA, bm, k0, tid);
        load_tile(stg + 2 * TILE_BYTES, Bh, ldB, bn, k0, tid);
        load_tile(stg + 3 * TILE_BYTES, Bl, ldB, bn, k0, tid);
    };

    // prologue: 2 chunks in flight
    load_chunk(sb, 0);
    CP_COMMIT();
    if (KC > 1) load_chunk(sb + STAGE_BYTES, 1);
    CP_COMMIT();

    // Double-buffered fragments
    uint32_t aH[2][2][4], aL[2][2][4], bHf[2][4][4], bLf[2][4][4];

    for (int c = 0; c < KC; c++) {
        if (c + 1 < KC) { CP_WAIT(1); } else { CP_WAIT(0); }
        __syncthreads();    // stage c%3 ready; everyone done reading stage (c+2)%3

        // loads for chunk c+2 into stage (c+2)%3 — overlap the MMAs below
        if (c + 2 < KC)
            load_chunk(sb + (uint32_t)((c + 2) % NSTAGE) * STAGE_BYTES, c + 2);
        CP_COMMIT();

        const uint32_t stg = sb + (uint32_t)(c % NSTAGE) * STAGE_BYTES;
        const uint32_t saH = stg;
        const uint32_t saL = stg + TILE_BYTES;
        const uint32_t sbH = stg + 2 * TILE_BYTES;
        const uint32_t sbL = stg + 3 * TILE_BYTES;

        // preload ks=0 fragments into buffer 0
        {
            #pragma unroll
            for (int mi = 0; mi < 2; mi++) {
                uint32_t so = sw((uint32_t)((a_row + mi * 16) * 128 + a_seg * 16));
                LDSM4(aH[0][mi][0], aH[0][mi][1], aH[0][mi][2], aH[0][mi][3], saH + so);
                LDSM4(aL[0][mi][0], aL[0][mi][1], aL[0][mi][2], aL[0][mi][3], saL + so);
            }
            #pragma unroll
            for (int ng = 0; ng < 4; ng++) {
                uint32_t so = sw((uint32_t)((b_row + ng * 16) * 128 + b_seg * 16));
                LDSM4(bHf[0][ng][0], bHf[0][ng][1], bHf[0][ng][2], bHf[0][ng][3], sbH + so);
                LDSM4(bLf[0][ng][0], bLf[0][ng][1], bLf[0][ng][2], bLf[0][ng][3], sbL + so);
            }
        }

        #pragma unroll
        for (int ks = 0; ks < 4; ks++) {
            const int cur = ks & 1;
            const int nxt = cur ^ 1;
            if (ks < 3) {
                // issue next ks's LDSMs before this ks's MMAs
                #pragma unroll
                for (int mi = 0; mi < 2; mi++) {
                    uint32_t so = sw((uint32_t)((a_row + mi * 16) * 128 +
                                                ((ks + 1) * 2 + a_seg) * 16));
                    LDSM4(aH[nxt][mi][0], aH[nxt][mi][1], aH[nxt][mi][2], aH[nxt][mi][3],
                          saH + so);
                    LDSM4(aL[nxt][mi][0], aL[nxt][mi][1], aL[nxt][mi][2], aL[nxt][mi][3],
                          saL + so);
                }
                #pragma unroll
                for (int ng = 0; ng < 4; ng++) {
                    uint32_t so = sw((uint32_t)((b_row + ng * 16) * 128 +
                                                ((ks + 1) * 2 + b_seg) * 16));
                    LDSM4(bHf[nxt][ng][0], bHf[nxt][ng][1], bHf[nxt][ng][2], bHf[nxt][ng][3],
                          sbH + so);
                    LDSM4(bLf[nxt][ng][0], bLf[nxt][ng][1], bLf[nxt][ng][2], bLf[nxt][ng][3],
                          sbL + so);
                }
            }
            #pragma unroll
            for (int mi = 0; mi < 2; mi++)
                #pragma unroll
                for (int nj = 0; nj < 8; nj++) {
                    const int ng = nj >> 1, hp = (nj & 1) << 1;
                    MMA_BF16(acc[mi][nj], aH[cur][mi], bHf[cur][ng][hp], bHf[cur][ng][hp + 1]);
                }
            #pragma unroll
            for (int mi = 0; mi < 2; mi++)
                #pragma unroll
                for (int nj = 0; nj < 8; nj++) {
                    const int ng = nj >> 1, hp = (nj & 1) << 1;
                    MMA_BF16(acc[mi][nj], aH[cur][mi], bLf[cur][ng][hp], bLf[cur][ng][hp + 1]);
                }
            #pragma unroll
            for (int mi = 0; mi < 2; mi++)
                #pragma unroll
                for (int nj = 0; nj < 8; nj++) {
                    const int ng = nj >> 1, hp = (nj & 1) << 1;
                    MMA_BF16(acc[mi][nj], aL[cur][mi], bHf[cur][ng][hp], bHf[cur][ng][hp + 1]);
                }
        }
        // no trailing sync: next iteration's top sync protects stage reuse
    }

    // ---------------- epilogue ----------------
    const int r0  = (lane >> 2);
    const int cth = 2 * (lane & 3);
    #pragma unroll
    for (int mi = 0; mi < 2; mi++) {
        #pragma unroll
        for (int nj = 0; nj < 8; nj++) {
            const int col = bn + wn * 64 + nj * 8 + cth;
            float v0 = acc[mi][nj][0], v1 = acc[mi][nj][1];
            float v2 = acc[mi][nj][2], v3 = acc[mi][nj][3];
            if (bias) {
                float b0 = bias[col], b1 = bias[col + 1];
                v0 += b0; v1 += b1; v2 += b0; v3 += b1;
            }
            const int rowA = bm + wm * 32 + mi * 16 + r0;
            const int rowB = rowA + 8;
            if (epi == 0) {
                *(float2*)&Cf[(size_t)rowA * N + col] = make_float2(v0, v1);
                *(float2*)&Cf[(size_t)rowB * N + col] = make_float2(v2, v3);
            } else {
                __nv_bfloat16 h0 = __float2bfloat16(v0);
                __nv_bfloat16 h1 = __float2bfloat16(v1);
                __nv_bfloat16 h2 = __float2bfloat16(v2);
                __nv_bfloat16 h3 = __float2bfloat16(v3);
                __nv_bfloat16 l0 = __float2bfloat16(v0 - __bfloat162float(h0));
                __nv_bfloat16 l1 = __float2bfloat16(v1 - __bfloat162float(h1));
                __nv_bfloat16 l2 = __float2bfloat16(v2 - __bfloat162float(h2));
                __nv_bfloat16 l3 = __float2bfloat16(v3 - __bfloat162float(h3));
                if (epi == 1) {
                    *(__nv_bfloat162*)&Ch[(size_t)rowA * N + col] = __nv_bfloat162(h0, h1);
                    *(__nv_bfloat162*)&Ch[(size_t)rowB * N + col] = __nv_bfloat162(h2, h3);
                    *(__nv_bfloat162*)&Cl[(size_t)rowA * N + col] = __nv_bfloat162(l0, l1);
                    *(__nv_bfloat162*)&Cl[(size_t)rowB * N + col] = __nv_bfloat162(l2, l3);
                } else {
                    Ch[(size_t)col * M + rowA]       = h0;
                    Ch[(size_t)(col + 1) * M + rowA] = h1;
                    Ch[(size_t)col * M + rowB]       = h2;
                    Ch[(size_t)(col + 1) * M + rowB] = h3;
                    Cl[(size_t)col * M + rowA]       = l0;
                    Cl[(size_t)(col + 1) * M + rowA] = l1;
                    Cl[(size_t)col * M + rowB]       = l2;
                    Cl[(size_t)(col + 1) * M + rowB] = l3;
                }
            }
        }
    }
}

// ---------------------------------------------------------------------------
// Kernel wrappers
// ---------------------------------------------------------------------------
__global__ __launch_bounds__(256, 1)
void proj_qkv(const __nv_bfloat16* __restrict__ Eh, const __nv_bfloat16* __restrict__ El,
              const __nv_bfloat16* __restrict__ Wqh, const __nv_bfloat16* __restrict__ Wql,
              const __nv_bfloat16* __restrict__ Wkh, const __nv_bfloat16* __restrict__ Wkl,
              const __nv_bfloat16* __restrict__ Wvh, const __nv_bfloat16* __restrict__ Wvl,
              const float* __restrict__ bq, const float* __restrict__ bk,
              const float* __restrict__ bv,
              __nv_bfloat16* __restrict__ Qh, __nv_bfloat16* __restrict__ Ql,
              __nv_bfloat16* __restrict__ Kh, __nv_bfloat16* __restrict__ Kl,
              __nv_bfloat16* __restrict__ VtH, __nv_bfloat16* __restrict__ VtL)
{
    extern __shared__ char smem[];
    const int z = blockIdx.z;
    const __nv_bfloat16* Bh = (z == 0) ? Wqh : (z == 1) ? Wkh : Wvh;
    const __nv_bfloat16* Bl = (z == 0) ? Wql : (z == 1) ? Wkl : Wvl;
    const float* bias       = (z == 0) ? bq  : (z == 1) ? bk  : bv;
    __nv_bfloat16* Ch       = (z == 0) ? Qh  : (z == 1) ? Kh  : VtH;
    __nv_bfloat16* Cl       = (z == 0) ? Ql  : (z == 1) ? Kl  : VtL;
    const int epi = (z == 2) ? 2 : 1;
    gemm3x_body(Eh, El, Bh, Bl, bias, nullptr, Ch, Cl,
                NTOK, DH, DIN, DIN, DIN, 0, epi, smem);
}

__global__ __launch_bounds__(256, 1)
void score_gemm(const __nv_bfloat16* __restrict__ Qh, const __nv_bfloat16* __restrict__ Ql,
                const __nv_bfloat16* __restrict__ Kh, const __nv_bfloat16* __restrict__ Kl,
                float* __restrict__ S)
{
    extern __shared__ char smem[];
    gemm3x_body(Qh, Ql, Kh, Kl, nullptr, S, nullptr, nullptr,
                NTOK, NTOK, DH, DH, DH, 0, 0, smem);
}

// PV unsplit: full K=4096 per CTA, direct fp32 store to out. 128 CTAs = 1 wave.
__global__ __launch_bounds__(256, 1)
void pv_gemm(const __nv_bfloat16* __restrict__ Ph, const __nv_bfloat16* __restrict__ Pl,
             const __nv_bfloat16* __restrict__ VtH, const __nv_bfloat16* __restrict__ VtL,
             float* __restrict__ out)
{
    extern __shared__ char smem[];
    gemm3x_body(Ph, Pl, VtH, VtL, nullptr, out, nullptr, nullptr,
                NTOK, DH, NTOK, NTOK, NTOK, 0, 0, smem);
}

// ---------------------------------------------------------------------------
// Row softmax over S[NTOK, NTOK], writes split bf16 P. 1 CTA/row.
// ---------------------------------------------------------------------------
__global__ __launch_bounds__(256)
void softmax_split(const float* __restrict__ S,
                   __nv_bfloat16* __restrict__ Ph, __nv_bfloat16* __restrict__ Pl)
{
    const int row = blockIdx.x;
    const float* p = S + (size_t)row * NTOK;
    const int tid = threadIdx.x;

    float vals[16];
    float m = -CUDART_INF_F;
    #pragma unroll
    for (int i = 0; i < 16; i++) {
        vals[i] = p[tid + i * 256];
        m = fmaxf(m, vals[i]);
    }

    __shared__ float red[8];
    #pragma unroll
    for (int o = 16; o > 0; o >>= 1)
        m = fmaxf(m, __shfl_xor_sync(0xffffffffu, m, o));
    if ((tid & 31) == 0) red[tid >> 5] = m;
    __syncthreads();
    if (tid < 32) {
        float x = (tid < 8) ? red[tid] : -CUDART_INF_F;
        #pragma unroll
        for (int o = 4; o > 0; o >>= 1)
            x = fmaxf(x, __shfl_xor_sync(0xffffffffu, x, o));
        if (tid == 0) red[0] = x;
    }
    __syncthreads();
    m = red[0];
    __syncthreads();

    float s = 0.0f;
    #pragma unroll
    for (int i = 0; i < 16; i++) {
        vals[i] = __expf(vals[i] - m);
        s += vals[i];
    }
    #pragma unroll
    for (int o = 16; o > 0; o >>= 1)
        s += __shfl_xor_sync(0xffffffffu, s, o);
    if ((tid & 31) == 0) red[tid >> 5] = s;
    __syncthreads();
    if (tid < 32) {
        float x = (tid < 8) ? red[tid] : 0.0f;
        #pragma unroll
        for (int o = 4; o > 0; o >>= 1)
            x += __shfl_xor_sync(0xffffffffu, x, o);
        if (tid == 0) red[0] = x;
    }
    __syncthreads();
    const float inv = 1.0f / red[0];

    __nv_bfloat16* ph = Ph + (size_t)row * NTOK;
    __nv_bfloat16* pl = Pl + (size_t)row * NTOK;
    #pragma unroll
    for (int i = 0; i < 16; i++) {
        float pv = vals[i] * inv;
        __nv_bfloat16 h = __float2bfloat16(pv);
        ph[tid + i * 256] = h;
        pl[tid + i * 256] = __float2bfloat16(pv - __bfloat162float(h));
    }
}

// ---------------------------------------------------------------------------
// Host launch
// ---------------------------------------------------------------------------
extern "C" void kernel_launch(void* const* d_in, const int* in_sizes, int n_in,
                              void* d_out, int out_size)
{
    const float* embs = (const float*)d_in[0];
    const float* Wq   = (const float*)d_in[1];
    const float* bq   = (const float*)d_in[2];
    const float* Wk   = (const float*)d_in[3];
    const float* bk   = (const float*)d_in[4];
    const float* Wv   = (const float*)d_in[5];
    const float* bv   = (const float*)d_in[6];
    float* out = (float*)d_out;

    __nv_bfloat16 *Eh, *El, *Wqh, *Wql, *Wkh, *Wkl, *Wvh, *Wvl;
    __nv_bfloat16 *Qh, *Ql, *Kh, *Kl, *VtH, *VtL, *Ph, *Pl;
    float *S;
    cudaGetSymbolAddress((void**)&Eh, g_Eh);   cudaGetSymbolAddress((void**)&El, g_El);
    cudaGetSymbolAddress((void**)&Wqh, g_Wqh); cudaGetSymbolAddress((void**)&Wql, g_Wql);
    cudaGetSymbolAddress((void**)&Wkh, g_Wkh); cudaGetSymbolAddress((void**)&Wkl, g_Wkl);
    cudaGetSymbolAddress((void**)&Wvh, g_Wvh); cudaGetSymbolAddress((void**)&Wvl, g_Wvl);
    cudaGetSymbolAddress((void**)&Qh, g_Qh);   cudaGetSymbolAddress((void**)&Ql, g_Ql);
    cudaGetSymbolAddress((void**)&Kh, g_Kh);   cudaGetSymbolAddress((void**)&Kl, g_Kl);
    cudaGetSymbolAddress((void**)&VtH, g_VtH); cudaGetSymbolAddress((void**)&VtL, g_VtL);
    cudaGetSymbolAddress((void**)&S, g_S);
    cudaGetSymbolAddress((void**)&Ph, g_Ph);   cudaGetSymbolAddress((void**)&Pl, g_Pl);

    cudaFuncSetAttribute(proj_qkv,   cudaFuncAttributeMaxDynamicSharedMemorySize, SMEM_BYTES);
    cudaFuncSetAttribute(score_gemm, cudaFuncAttributeMaxDynamicSharedMemorySize, SMEM_BYTES);
    cudaFuncSetAttribute(pv_gemm,    cudaFuncAttributeMaxDynamicSharedMemorySize, SMEM_BYTES);

    // 1) hi/lo splits
    split_f32<<<2048, 256>>>((const float4*)embs, (__nv_bfloat162*)Eh,
                             (__nv_bfloat162*)El, NTOK * DIN / 4);
    dim3 g_w(256, 1, 3);
    split_w3<<<g_w, 256>>>((const float4*)Wq, (const float4*)Wk, (const float4*)Wv,
                           (__nv_bfloat162*)Wqh, (__nv_bfloat162*)Wql,
                           (__nv_bfloat162*)Wkh, (__nv_bfloat162*)Wkl,
                           (__nv_bfloat162*)Wvh, (__nv_bfloat162*)Wvl,
                           DH * DIN / 4);

    // 2) Q/K/V projections in ONE launch (384 CTAs)
    dim3 g_proj(DH / 128, NTOK / 128, 3);
    proj_qkv<<<g_proj, 256, SMEM_BYTES>>>(Eh, El, Wqh, Wql, Wkh, Wkl, Wvh, Wvl,
                                          bq, bk, bv, Qh, Ql, Kh, Kl, VtH, VtL);

    // 3) scores S = Q @ K^T (1024 CTAs)
    dim3 g_s(NTOK / 128, NTOK / 128);
    score_gemm<<<g_s, 256, SMEM_BYTES>>>(Qh, Ql, Kh, Kl, S);

    // 4) softmax + P split
    softmax_split<<<NTOK, 256>>>(S, Ph, Pl);

    // 5) out = P @ V, unsplit K (128 CTAs, one wave, no reduce)
    dim3 g_pv(DH / 128, NTOK / 128);
    pv_gemm<<<g_pv, 256, SMEM_BYTES>>>(Ph, Pl, VtH, VtL, out);
}